// round 15
// baseline (speedup 1.0000x reference)
#include <cuda_runtime.h>
#include <cuda_fp16.h>
#include <math.h>
#include <stdint.h>

// Problem constants
#define BB   8
#define SS   1024
#define DD   1024
#define HH   16
#define DKK  64
#define MM   (BB*SS)          // 8192 global rows
#define L2E  1.4426950408889634f

// ---------------- device scratch (no allocs allowed) ----------------
__device__ __half g_nh[MM*DD];    // normed hi
__device__ __half g_nl[MM*DD];    // normed lo
__device__ __half g_wq[DD*DD];
__device__ __half g_wk[DD*DD];
__device__ __half g_wv[DD*DD];
__device__ __half g_wo[DD*DD];
__device__ __half g_qh[MM*DD];    // [m][h*64+dk], pre-scaled by log2(e)
__device__ __half g_ql[MM*DD];
__device__ __half g_kh[MM*DD];
__device__ __half g_kl[MM*DD];
__device__ __half g_vh[MM*DD];    // V: hi only
__device__ __half g_ch[MM*DD];    // ctx: hi only
__device__ float  g_bias[HH*2048]; // [h][delta+1023] * log2(e)

// ---------------- PTX helpers ----------------
__device__ __forceinline__ uint32_t sptr(const void* p) {
    return (uint32_t)__cvta_generic_to_shared(p);
}
__device__ __forceinline__ float ex2f(float x) {
    float r; asm("ex2.approx.f32 %0,%1;" : "=f"(r) : "f"(x)); return r;
}
__device__ __forceinline__ void ldsm4(uint32_t a, uint32_t* r) {
    asm volatile("ldmatrix.sync.aligned.m8n8.x4.shared.b16 {%0,%1,%2,%3},[%4];"
        : "=r"(r[0]), "=r"(r[1]), "=r"(r[2]), "=r"(r[3]) : "r"(a));
}
__device__ __forceinline__ void ldsm4t(uint32_t a, uint32_t* r) {
    asm volatile("ldmatrix.sync.aligned.m8n8.x4.trans.shared.b16 {%0,%1,%2,%3},[%4];"
        : "=r"(r[0]), "=r"(r[1]), "=r"(r[2]), "=r"(r[3]) : "r"(a));
}
__device__ __forceinline__ void mma16816(float* c,
    uint32_t a0, uint32_t a1, uint32_t a2, uint32_t a3,
    uint32_t b0, uint32_t b1) {
    asm volatile(
        "mma.sync.aligned.m16n8k16.row.col.f32.f16.f16.f32 "
        "{%0,%1,%2,%3},{%4,%5,%6,%7},{%8,%9},{%0,%1,%2,%3};"
        : "+f"(c[0]), "+f"(c[1]), "+f"(c[2]), "+f"(c[3])
        : "r"(a0), "r"(a1), "r"(a2), "r"(a3), "r"(b0), "r"(b1));
}
__device__ __forceinline__ void cpa(uint32_t dst, const void* src) {
    asm volatile("cp.async.cg.shared.global [%0],[%1],16;" :: "r"(dst), "l"(src));
}
#define CP_COMMIT asm volatile("cp.async.commit_group;")
#define CP_WAIT1  asm volatile("cp.async.wait_group 1;")
#define CP_WAIT0  asm volatile("cp.async.wait_group 0;")

// ---------------- prep: fp16 weights + relative-position bias table ----------------
__global__ __launch_bounds__(256) void prep_kernel(
    const float* __restrict__ wq, const float* __restrict__ wk,
    const float* __restrict__ wv, const float* __restrict__ wo,
    const float* __restrict__ rel_bias)
{
    int i = blockIdx.x * 256 + threadIdx.x;
    if (i < DD*DD) {
        g_wq[i] = __float2half(wq[i]);
        g_wk[i] = __float2half(wk[i]);
        g_wv[i] = __float2half(wv[i]);
        g_wo[i] = __float2half(wo[i]);
    }
    if (i < HH*2048) {
        int h    = i >> 11;
        int dpos = i & 2047;
        int delta = dpos - 1023;
        int bucket = (delta > 0) ? 16 : 0;
        int rp = (delta < 0) ? -delta : delta;
        int add;
        if (rp < 8) {
            add = rp;
        } else {
            float t = logf((float)rp * 0.125f);
            float v = t / 2.772588722239781f * 8.0f;
            add = 8 + (int)v;
            if (add > 15) add = 15;
        }
        g_bias[i] = rel_bias[(bucket + add) * HH + h] * L2E;
    }
}

// ---------------- T5 RMSNorm -> fp16 hi/lo ----------------
__global__ __launch_bounds__(256) void rms_kernel(
    const float* __restrict__ x, const float* __restrict__ w)
{
    int row = blockIdx.x;
    const float4* xr = (const float4*)(x + (size_t)row * DD);
    float4 v = xr[threadIdx.x];
    float ss = v.x*v.x + v.y*v.y + v.z*v.z + v.w*v.w;
    #pragma unroll
    for (int o = 16; o; o >>= 1) ss += __shfl_xor_sync(0xffffffffu, ss, o);
    __shared__ float ws[8];
    if ((threadIdx.x & 31) == 0) ws[threadIdx.x >> 5] = ss;
    __syncthreads();
    float tot = 0.f;
    #pragma unroll
    for (int i = 0; i < 8; i++) tot += ws[i];
    float scale = rsqrtf(tot * (1.f/1024.f) + 1e-6f);
    float4 wv = ((const float4*)w)[threadIdx.x];
    float y0 = wv.x * (v.x*scale), y1 = wv.y * (v.y*scale);
    float y2 = wv.z * (v.z*scale), y3 = wv.w * (v.w*scale);
    __half h0 = __float2half_rn(y0), h1 = __float2half_rn(y1);
    __half h2 = __float2half_rn(y2), h3 = __float2half_rn(y3);
    __half l0 = __float2half_rn(y0 - __half2float(h0));
    __half l1 = __float2half_rn(y1 - __half2float(h1));
    __half l2 = __float2half_rn(y2 - __half2float(h2));
    __half l3 = __float2half_rn(y3 - __half2float(h3));
    __half2* oh = (__half2*)(g_nh + (size_t)row * DD) + threadIdx.x*2;
    __half2* ol = (__half2*)(g_nl + (size_t)row * DD) + threadIdx.x*2;
    oh[0] = __halves2half2(h0, h1); oh[1] = __halves2half2(h2, h3);
    ol[0] = __halves2half2(l0, l1); ol[1] = __halves2half2(l2, l3);
}

// ---------------- shared GEMM mainloop (mma.sync, warp tile 64x64) ----------------
#define G_ALD 40
#define G_BLD 136
#define G_ASZ (128*G_ALD)

struct GAcc { float c[4][8][4]; };   // [m-tile][n-tile][quad]

template<bool HAS_LO, int NST>
__device__ __forceinline__ void gemm_mainloop(
    const __half* __restrict__ Ah, const __half* __restrict__ Al,
    const __half* __restrict__ W, int m0, int n0, char* smem, GAcc& g)
{
    constexpr int NA  = HAS_LO ? 2 : 1;
    constexpr int BO  = NA * G_ASZ;              // B offset (halfs)
    constexpr int STG = BO + 32*G_BLD;           // halfs per stage

    const int tid = threadIdx.x, lane = tid & 31, warp = tid >> 5;
    const int wm = warp >> 1, wn = warp & 1;
    __half* S = (__half*)smem;

    #pragma unroll
    for (int i = 0; i < 4; i++)
        #pragma unroll
        for (int j = 0; j < 8; j++)
            #pragma unroll
            for (int q = 0; q < 4; q++) g.c[i][j][q] = 0.f;

    auto load_stage = [&](int st, int k0) {
        __half* base = S + st * STG;
        #pragma unroll
        for (int i = 0; i < 4; i++) {
            int c = tid + i*128;
            int r = c >> 2, cc = (c & 3) * 8;
            cpa(sptr(base + r*G_ALD + cc), Ah + (size_t)(m0 + r)*DD + k0 + cc);
            if (HAS_LO)
                cpa(sptr(base + G_ASZ + r*G_ALD + cc), Al + (size_t)(m0 + r)*DD + k0 + cc);
        }
        #pragma unroll
        for (int i = 0; i < 4; i++) {
            int c = tid + i*128;
            int r = c >> 4, cc = (c & 15) * 8;
            cpa(sptr(base + BO + r*G_BLD + cc), W + (size_t)(k0 + r)*DD + n0 + cc);
        }
    };

    #pragma unroll
    for (int p = 0; p < NST-1; p++) { load_stage(p, p*32); CP_COMMIT; }

    const int arow = (lane & 7) + ((lane >> 3) & 1) * 8;
    const int acol = (lane >> 4) * 8;
    const int brow = lane & 15;
    const int bcol = (lane >> 4) * 8;

    for (int kt = 0; kt < 32; kt++) {
        if (NST == 3 && kt < 31) { CP_WAIT1; } else { CP_WAIT0; }
        __syncthreads();
        if (kt + NST - 1 < 32) { load_stage((kt + NST - 1) % NST, (kt + NST - 1)*32); CP_COMMIT; }

        __half* base = S + (kt % NST) * STG;
        #pragma unroll
        for (int k16 = 0; k16 < 2; k16++) {
            uint32_t ah[4][4], al[4][4];
            #pragma unroll
            for (int mt = 0; mt < 4; mt++) {
                uint32_t ad = sptr(base + (wm*64 + mt*16 + arow)*G_ALD + k16*16 + acol);
                ldsm4(ad, ah[mt]);
                if (HAS_LO) ldsm4(ad + (uint32_t)(G_ASZ*2), al[mt]);
            }
            #pragma unroll
            for (int nb = 0; nb < 4; nb++) {
                uint32_t b[4];
                ldsm4t(sptr(base + BO + (k16*16 + brow)*G_BLD + wn*64 + nb*16 + bcol), b);
                #pragma unroll
                for (int mt = 0; mt < 4; mt++) {
                    mma16816(g.c[mt][2*nb  ], ah[mt][0], ah[mt][1], ah[mt][2], ah[mt][3], b[0], b[1]);
                    mma16816(g.c[mt][2*nb+1], ah[mt][0], ah[mt][1], ah[mt][2], ah[mt][3], b[2], b[3]);
                    if (HAS_LO) {
                        mma16816(g.c[mt][2*nb  ], al[mt][0], al[mt][1], al[mt][2], al[mt][3], b[0], b[1]);
                        mma16816(g.c[mt][2*nb+1], al[mt][0], al[mt][1], al[mt][2], al[mt][3], b[2], b[3]);
                    }
                }
            }
        }
    }
}

#define GEMM_SMEM_QK  (2*(2*G_ASZ + 32*G_BLD)*2)   // 2 stages, hi+lo A  (58.4KB)
#define GEMM_SMEM_LO  (3*(1*G_ASZ + 32*G_BLD)*2)   // 3 stages, hi-only A (56.8KB)

// Q/K projection: z selects q/k. Output hi/lo halves. Q scaled by log2(e).
__global__ __launch_bounds__(128) void projqk_kernel()
{
    extern __shared__ __align__(16) char smem[];
    int z = blockIdx.z;
    const __half* W = (z == 0) ? g_wq : g_wk;
    __half* Chi = (z == 0) ? g_qh : g_kh;
    __half* Clo = (z == 0) ? g_ql : g_kl;
    float oscale = (z == 0) ? L2E : 1.0f;
    int m0 = blockIdx.x * 128, n0 = blockIdx.y * 128;

    GAcc g;
    gemm_mainloop<true, 2>(g_nh, g_nl, W, m0, n0, smem, g);

    int lane = threadIdx.x & 31, warp = threadIdx.x >> 5;
    int wm = warp >> 1, wn = warp & 1;
    #pragma unroll
    for (int mt = 0; mt < 4; mt++)
        #pragma unroll
        for (int nt = 0; nt < 8; nt++) {
            int row = m0 + wm*64 + mt*16 + (lane >> 2);
            int col = n0 + wn*64 + nt*8 + (lane & 3)*2;
            #pragma unroll
            for (int hfr = 0; hfr < 2; hfr++) {
                float v0 = g.c[mt][nt][hfr*2] * oscale, v1 = g.c[mt][nt][hfr*2+1] * oscale;
                __half h0 = __float2half_rn(v0), h1 = __float2half_rn(v1);
                __half l0 = __float2half_rn(v0 - __half2float(h0));
                __half l1 = __float2half_rn(v1 - __half2float(h1));
                size_t gi = (size_t)(row + hfr*8)*DD + col;
                *(__half2*)(Chi + gi) = __halves2half2(h0, h1);
                *(__half2*)(Clo + gi) = __halves2half2(l0, l1);
            }
        }
}

// V projection: A hi only, output hi only.
__global__ __launch_bounds__(128) void projv_kernel()
{
    extern __shared__ __align__(16) char smem[];
    int m0 = blockIdx.x * 128, n0 = blockIdx.y * 128;

    GAcc g;
    gemm_mainloop<false, 3>(g_nh, (const __half*)0, g_wv, m0, n0, smem, g);

    int lane = threadIdx.x & 31, warp = threadIdx.x >> 5;
    int wm = warp >> 1, wn = warp & 1;
    #pragma unroll
    for (int mt = 0; mt < 4; mt++)
        #pragma unroll
        for (int nt = 0; nt < 8; nt++) {
            int row = m0 + wm*64 + mt*16 + (lane >> 2);
            int col = n0 + wn*64 + nt*8 + (lane & 3)*2;
            #pragma unroll
            for (int hfr = 0; hfr < 2; hfr++) {
                size_t gi = (size_t)(row + hfr*8)*DD + col;
                *(__half2*)(g_vh + gi) =
                    __floats2half2_rn(g.c[mt][nt][hfr*2], g.c[mt][nt][hfr*2+1]);
            }
        }
}

// Output projection + residual -> fp32 out (A = ctx hi only)
__global__ __launch_bounds__(128) void oproj_kernel(
    const float* __restrict__ hid, float* __restrict__ out)
{
    extern __shared__ __align__(16) char smem[];
    int m0 = blockIdx.x * 128, n0 = blockIdx.y * 128;

    GAcc g;
    gemm_mainloop<false, 3>(g_ch, (const __half*)0, g_wo, m0, n0, smem, g);

    int lane = threadIdx.x & 31, warp = threadIdx.x >> 5;
    int wm = warp >> 1, wn = warp & 1;
    #pragma unroll
    for (int mt = 0; mt < 4; mt++)
        #pragma unroll
        for (int nt = 0; nt < 8; nt++) {
            int row = m0 + wm*64 + mt*16 + (lane >> 2);
            int col = n0 + wn*64 + nt*8 + (lane & 3)*2;
            #pragma unroll
            for (int hfr = 0; hfr < 2; hfr++) {
                size_t gi = (size_t)(row + hfr*8)*DD + col;
                float2 r = *(const float2*)(hid + gi);
                float2 o;
                o.x = g.c[mt][nt][hfr*2]   + r.x;
                o.y = g.c[mt][nt][hfr*2+1] + r.y;
                *(float2*)(out + gi) = o;
            }
        }
}

// ---------------- flash attention (FA2, register-resident, mma.sync) ----------------
// grid (SS/128=8, B*H=128), 128 threads = 4 warps, each warp 32 q-rows
// (2 m-tiles of 16). BM=128, BN=64. Q/K hi+lo (3-mma S), V hi only.
// Logits pre-scaled by log2(e) -> ex2. K/V/bias frags amortized over 2 m-tiles.
#define AT_LD 72
#define AT_KVA (64*AT_LD)      // halfs per KV array
#define AT_KVS (3*AT_KVA)      // halfs per stage (Kh,Kl,Vh)
#define ATTN_SMEM ((2*128*AT_LD + 2*AT_KVS)*2)

__global__ __launch_bounds__(128, 2) void attn_kernel()
{
    extern __shared__ __align__(16) char smem[];
    __half* Qh = (__half*)smem;                 // [128][AT_LD]
    __half* Ql = Qh + 128*AT_LD;
    __half* KV = Ql + 128*AT_LD;                // [2 stages][3 arrays][64*AT_LD]

    int tid = threadIdx.x, lane = tid & 31, warp = tid >> 5;
    int q0 = blockIdx.x * 128;
    int bh = blockIdx.y;
    int b = bh >> 4, h = bh & 15;
    size_t qg = ((size_t)(b*SS + q0)) * DD + h*DKK;

    #pragma unroll
    for (int i = 0; i < 8; i++) {
        int c = tid + i*128; int r = c >> 3, cc = (c & 7) * 8;
        cpa(sptr(Qh + r*AT_LD + cc), g_qh + qg + (size_t)r*DD + cc);
        cpa(sptr(Ql + r*AT_LD + cc), g_ql + qg + (size_t)r*DD + cc);
    }

    auto load_kv = [&](int st, int k0) {
        size_t kg = ((size_t)(b*SS + k0)) * DD + h*DKK;
        __half* s0 = KV + st * AT_KVS;
        #pragma unroll
        for (int i = 0; i < 4; i++) {
            int c = tid + i*128; int r = c >> 3, cc = (c & 7) * 8;
            cpa(sptr(s0 + 0*AT_KVA + r*AT_LD + cc), g_kh + kg + (size_t)r*DD + cc);
            cpa(sptr(s0 + 1*AT_KVA + r*AT_LD + cc), g_kl + kg + (size_t)r*DD + cc);
            cpa(sptr(s0 + 2*AT_KVA + r*AT_LD + cc), g_vh + kg + (size_t)r*DD + cc);
        }
    };
    load_kv(0, 0); CP_COMMIT;

    float o[2][8][4];
    #pragma unroll
    for (int mt = 0; mt < 2; mt++)
        #pragma unroll
        for (int i = 0; i < 8; i++)
            #pragma unroll
            for (int j = 0; j < 4; j++) o[mt][i][j] = 0.f;
    float mr[2][2], lr[2][2];
    #pragma unroll
    for (int mt = 0; mt < 2; mt++) {
        mr[mt][0] = -1e30f; mr[mt][1] = -1e30f;
        lr[mt][0] = 0.f;    lr[mt][1] = 0.f;
    }

    const int arow = (lane & 7) + ((lane >> 3) & 1) * 8;
    const int acol = (lane >> 4) * 8;
    const int trow = lane & 15;
    const int tcol = (lane >> 4) * 8;
    int qrow0 = warp*32 + (lane >> 2);
    const float* biasm[2];
    biasm[0] = g_bias + h*2048 + 1023 - (q0 + qrow0);
    biasm[1] = biasm[0] - 16;

    for (int j = 0; j < 16; j++) {
        if (j + 1 < 16) { load_kv((j+1)&1, (j+1)*64); CP_COMMIT; CP_WAIT1; }
        else { CP_WAIT0; }
        __syncthreads();
        __half* st  = KV + (j & 1) * AT_KVS;
        __half* KhS = st;
        __half* VhS = st + 2*AT_KVA;

        float s[2][8][4];
        #pragma unroll
        for (int mt = 0; mt < 2; mt++)
            #pragma unroll
            for (int i = 0; i < 8; i++)
                #pragma unroll
                for (int q = 0; q < 4; q++) s[mt][i][q] = 0.f;

        #pragma unroll
        for (int kk = 0; kk < 4; kk++) {
            uint32_t ah[2][4], al[2][4];
            #pragma unroll
            for (int mt = 0; mt < 2; mt++) {
                uint32_t qa = sptr(Qh + (warp*32 + mt*16 + arow)*AT_LD + kk*16 + acol);
                ldsm4(qa, ah[mt]);
                ldsm4(qa + (uint32_t)(128*AT_LD*2), al[mt]);
            }
            #pragma unroll
            for (int nb = 0; nb < 4; nb++) {
                uint32_t bh4[4], bl4[4];
                uint32_t ka = sptr(KhS + (nb*16 + arow)*AT_LD + kk*16 + acol);
                ldsm4(ka, bh4);
                ldsm4(ka + (uint32_t)(AT_KVA*2), bl4);
                #pragma unroll
                for (int mt = 0; mt < 2; mt++) {
                    mma16816(s[mt][2*nb  ], ah[mt][0],ah[mt][1],ah[mt][2],ah[mt][3], bh4[0], bh4[2]);
                    mma16816(s[mt][2*nb+1], ah[mt][0],ah[mt][1],ah[mt][2],ah[mt][3], bh4[1], bh4[3]);
                    mma16816(s[mt][2*nb  ], ah[mt][0],ah[mt][1],ah[mt][2],ah[mt][3], bl4[0], bl4[2]);
                    mma16816(s[mt][2*nb+1], ah[mt][0],ah[mt][1],ah[mt][2],ah[mt][3], bl4[1], bl4[3]);
                    mma16816(s[mt][2*nb  ], al[mt][0],al[mt][1],al[mt][2],al[mt][3], bh4[0], bh4[2]);
                    mma16816(s[mt][2*nb+1], al[mt][0],al[mt][1],al[mt][2],al[mt][3], bh4[1], bh4[3]);
                }
            }
        }

        int kb = j*64;
        uint32_t u[2][8], w[2][8];
        #pragma unroll
        for (int mt = 0; mt < 2; mt++) {
            const float* bias0 = biasm[mt];
            float mx0 = -1e30f, mx1 = -1e30f;
            #pragma unroll
            for (int nt = 0; nt < 8; nt++) {
                int col = kb + nt*8 + (lane & 3)*2;
                s[mt][nt][0] += bias0[col];     s[mt][nt][1] += bias0[col+1];
                s[mt][nt][2] += bias0[col-8];   s[mt][nt][3] += bias0[col-7];
                mx0 = fmaxf(mx0, fmaxf(s[mt][nt][0], s[mt][nt][1]));
                mx1 = fmaxf(mx1, fmaxf(s[mt][nt][2], s[mt][nt][3]));
            }
            mx0 = fmaxf(mx0, __shfl_xor_sync(0xffffffffu, mx0, 1));
            mx0 = fmaxf(mx0, __shfl_xor_sync(0xffffffffu, mx0, 2));
            mx1 = fmaxf(mx1, __shfl_xor_sync(0xffffffffu, mx1, 1));
            mx1 = fmaxf(mx1, __shfl_xor_sync(0xffffffffu, mx1, 2));
            float nm0 = fmaxf(mr[mt][0], mx0), nm1 = fmaxf(mr[mt][1], mx1);
            float sc0 = ex2f(mr[mt][0] - nm0), sc1 = ex2f(mr[mt][1] - nm1);
            mr[mt][0] = nm0; mr[mt][1] = nm1;

            float sum0 = 0.f, sum1 = 0.f;
            #pragma unroll
            for (int nt = 0; nt < 8; nt++) {
                float p0 = ex2f(s[mt][nt][0] - nm0), p1 = ex2f(s[mt][nt][1] - nm0);
                float p2 = ex2f(s[mt][nt][2] - nm1), p3 = ex2f(s[mt][nt][3] - nm1);
                sum0 += p0 + p1; sum1 += p2 + p3;
                __half2 h01 = __floats2half2_rn(p0, p1);
                __half2 h23 = __floats2half2_rn(p2, p3);
                u[mt][nt] = *(uint32_t*)&h01;
                w[mt][nt] = *(uint32_t*)&h23;
                o[mt][nt][0] *= sc0; o[mt][nt][1] *= sc0;
                o[mt][nt][2] *= sc1; o[mt][nt][3] *= sc1;
            }
            sum0 += __shfl_xor_sync(0xffffffffu, sum0, 1);
            sum0 += __shfl_xor_sync(0xffffffffu, sum0, 2);
            sum1 += __shfl_xor_sync(0xffffffffu, sum1, 1);
            sum1 += __shfl_xor_sync(0xffffffffu, sum1, 2);
            lr[mt][0] = lr[mt][0]*sc0 + sum0;
            lr[mt][1] = lr[mt][1]*sc1 + sum1;
        }

        #pragma unroll
        for (int kk = 0; kk < 4; kk++) {
            #pragma unroll
            for (int nb = 0; nb < 4; nb++) {
                uint32_t vh4[4];
                ldsm4t(sptr(VhS + (kk*16 + trow)*AT_LD + nb*16 + tcol), vh4);
                #pragma unroll
                for (int mt = 0; mt < 2; mt++) {
                    mma16816(o[mt][2*nb  ], u[mt][2*kk], w[mt][2*kk], u[mt][2*kk+1], w[mt][2*kk+1], vh4[0], vh4[1]);
                    mma16816(o[mt][2*nb+1], u[mt][2*kk], w[mt][2*kk], u[mt][2*kk+1], w[mt][2*kk+1], vh4[2], vh4[3]);
                }
            }
        }
        __syncthreads();
    }

    #pragma unroll
    for (int mt = 0; mt < 2; mt++) {
        float inv0 = 1.f / lr[mt][0], inv1 = 1.f / lr[mt][1];
        #pragma unroll
        for (int nt = 0; nt < 8; nt++) {
            int col = h*DKK + nt*8 + (lane & 3)*2;
            size_t r0 = ((size_t)(b*SS + q0 + qrow0 + mt*16)) * DD + col;
            size_t r1 = r0 + (size_t)8*DD;
            float v0 = o[mt][nt][0]*inv0, v1 = o[mt][nt][1]*inv0;
            float v2 = o[mt][nt][2]*inv1, v3 = o[mt][nt][3]*inv1;
            *(__half2*)(g_ch + r0) = __floats2half2_rn(v0, v1);
            *(__half2*)(g_ch + r1) = __floats2half2_rn(v2, v3);
        }
    }
}

// ---------------- launch ----------------
extern "C" void kernel_launch(void* const* d_in, const int* in_sizes, int n_in,
                              void* d_out, int out_size)
{
    const float* hid  = (const float*)d_in[0];
    const float* lnw  = (const float*)d_in[1];
    const float* wq   = (const float*)d_in[2];
    const float* wk   = (const float*)d_in[3];
    const float* wv   = (const float*)d_in[4];
    const float* wo   = (const float*)d_in[5];
    const float* relb = (const float*)d_in[6];
    float* out = (float*)d_out;

    cudaFuncSetAttribute(attn_kernel,   cudaFuncAttributeMaxDynamicSharedMemorySize, ATTN_SMEM);
    cudaFuncSetAttribute(projqk_kernel, cudaFuncAttributeMaxDynamicSharedMemorySize, GEMM_SMEM_QK);
    cudaFuncSetAttribute(projv_kernel,  cudaFuncAttributeMaxDynamicSharedMemorySize, GEMM_SMEM_LO);
    cudaFuncSetAttribute(oproj_kernel,  cudaFuncAttributeMaxDynamicSharedMemorySize, GEMM_SMEM_LO);

    prep_kernel<<<(DD*DD + 255)/256, 256>>>(wq, wk, wv, wo, relb);
    rms_kernel<<<MM, 256>>>(hid, lnw);
    projqk_kernel<<<dim3(MM/128, DD/128, 2), 128, GEMM_SMEM_QK>>>();
    projv_kernel<<<dim3(MM/128, DD/128), 128, GEMM_SMEM_LO>>>();
    attn_kernel<<<dim3(SS/128, BB*HH), 128, ATTN_SMEM>>>();
    oproj_kernel<<<dim3(MM/128, DD/128), 128, GEMM_SMEM_LO>>>(hid, out);
}

// round 16
// speedup vs baseline: 1.0849x; 1.0849x over previous
#include <cuda_runtime.h>
#include <cuda_fp16.h>
#include <math.h>
#include <stdint.h>

// Problem constants
#define BB   8
#define SS   1024
#define DD   1024
#define HH   16
#define DKK  64
#define MM   (BB*SS)          // 8192 global rows
#define L2E  1.4426950408889634f

// ---------------- device scratch (no allocs allowed) ----------------
__device__ __half g_nh[MM*DD];    // normed hi
__device__ __half g_nl[MM*DD];    // normed lo
__device__ __half g_wq[DD*DD];
__device__ __half g_wk[DD*DD];
__device__ __half g_wv[DD*DD];
__device__ __half g_wo[DD*DD];
__device__ __half g_qh[MM*DD];    // [m][h*64+dk], pre-scaled by log2(e), hi only
__device__ __half g_kh[MM*DD];
__device__ __half g_kl[MM*DD];
__device__ __half g_vh[MM*DD];    // V: hi only
__device__ __half g_ch[MM*DD];    // ctx: hi only
__device__ float  g_bias[HH*2048]; // [h][delta+1023] * log2(e)

// ---------------- PTX helpers ----------------
__device__ __forceinline__ uint32_t sptr(const void* p) {
    return (uint32_t)__cvta_generic_to_shared(p);
}
__device__ __forceinline__ float ex2f(float x) {
    float r; asm("ex2.approx.f32 %0,%1;" : "=f"(r) : "f"(x)); return r;
}
__device__ __forceinline__ void ldsm4(uint32_t a, uint32_t* r) {
    asm volatile("ldmatrix.sync.aligned.m8n8.x4.shared.b16 {%0,%1,%2,%3},[%4];"
        : "=r"(r[0]), "=r"(r[1]), "=r"(r[2]), "=r"(r[3]) : "r"(a));
}
__device__ __forceinline__ void ldsm4t(uint32_t a, uint32_t* r) {
    asm volatile("ldmatrix.sync.aligned.m8n8.x4.trans.shared.b16 {%0,%1,%2,%3},[%4];"
        : "=r"(r[0]), "=r"(r[1]), "=r"(r[2]), "=r"(r[3]) : "r"(a));
}
__device__ __forceinline__ void mma16816(float* c,
    uint32_t a0, uint32_t a1, uint32_t a2, uint32_t a3,
    uint32_t b0, uint32_t b1) {
    asm volatile(
        "mma.sync.aligned.m16n8k16.row.col.f32.f16.f16.f32 "
        "{%0,%1,%2,%3},{%4,%5,%6,%7},{%8,%9},{%0,%1,%2,%3};"
        : "+f"(c[0]), "+f"(c[1]), "+f"(c[2]), "+f"(c[3])
        : "r"(a0), "r"(a1), "r"(a2), "r"(a3), "r"(b0), "r"(b1));
}
__device__ __forceinline__ void cpa(uint32_t dst, const void* src) {
    asm volatile("cp.async.cg.shared.global [%0],[%1],16;" :: "r"(dst), "l"(src));
}
#define CP_COMMIT asm volatile("cp.async.commit_group;")
#define CP_WAIT1  asm volatile("cp.async.wait_group 1;")
#define CP_WAIT0  asm volatile("cp.async.wait_group 0;")

// ---------------- prep: fp16 weights + relative-position bias table ----------------
__global__ __launch_bounds__(256) void prep_kernel(
    const float* __restrict__ wq, const float* __restrict__ wk,
    const float* __restrict__ wv, const float* __restrict__ wo,
    const float* __restrict__ rel_bias)
{
    int i = blockIdx.x * 256 + threadIdx.x;
    if (i < DD*DD) {
        g_wq[i] = __float2half(wq[i]);
        g_wk[i] = __float2half(wk[i]);
        g_wv[i] = __float2half(wv[i]);
        g_wo[i] = __float2half(wo[i]);
    }
    if (i < HH*2048) {
        int h    = i >> 11;
        int dpos = i & 2047;
        int delta = dpos - 1023;
        int bucket = (delta > 0) ? 16 : 0;
        int rp = (delta < 0) ? -delta : delta;
        int add;
        if (rp < 8) {
            add = rp;
        } else {
            float t = logf((float)rp * 0.125f);
            float v = t / 2.772588722239781f * 8.0f;
            add = 8 + (int)v;
            if (add > 15) add = 15;
        }
        g_bias[i] = rel_bias[(bucket + add) * HH + h] * L2E;
    }
}

// ---------------- T5 RMSNorm -> fp16 hi/lo ----------------
__global__ __launch_bounds__(256) void rms_kernel(
    const float* __restrict__ x, const float* __restrict__ w)
{
    int row = blockIdx.x;
    const float4* xr = (const float4*)(x + (size_t)row * DD);
    float4 v = xr[threadIdx.x];
    float ss = v.x*v.x + v.y*v.y + v.z*v.z + v.w*v.w;
    #pragma unroll
    for (int o = 16; o; o >>= 1) ss += __shfl_xor_sync(0xffffffffu, ss, o);
    __shared__ float ws[8];
    if ((threadIdx.x & 31) == 0) ws[threadIdx.x >> 5] = ss;
    __syncthreads();
    float tot = 0.f;
    #pragma unroll
    for (int i = 0; i < 8; i++) tot += ws[i];
    float scale = rsqrtf(tot * (1.f/1024.f) + 1e-6f);
    float4 wv = ((const float4*)w)[threadIdx.x];
    float y0 = wv.x * (v.x*scale), y1 = wv.y * (v.y*scale);
    float y2 = wv.z * (v.z*scale), y3 = wv.w * (v.w*scale);
    __half h0 = __float2half_rn(y0), h1 = __float2half_rn(y1);
    __half h2 = __float2half_rn(y2), h3 = __float2half_rn(y3);
    __half l0 = __float2half_rn(y0 - __half2float(h0));
    __half l1 = __float2half_rn(y1 - __half2float(h1));
    __half l2 = __float2half_rn(y2 - __half2float(h2));
    __half l3 = __float2half_rn(y3 - __half2float(h3));
    __half2* oh = (__half2*)(g_nh + (size_t)row * DD) + threadIdx.x*2;
    __half2* ol = (__half2*)(g_nl + (size_t)row * DD) + threadIdx.x*2;
    oh[0] = __halves2half2(h0, h1); oh[1] = __halves2half2(h2, h3);
    ol[0] = __halves2half2(l0, l1); ol[1] = __halves2half2(l2, l3);
}

// ---------------- shared GEMM mainloop (mma.sync, warp tile 64x64) ----------------
#define G_ALD 40
#define G_BLD 136
#define G_ASZ (128*G_ALD)

struct GAcc { float c[4][8][4]; };   // [m-tile][n-tile][quad]

template<bool HAS_LO, int NST>
__device__ __forceinline__ void gemm_mainloop(
    const __half* __restrict__ Ah, const __half* __restrict__ Al,
    const __half* __restrict__ W, int m0, int n0, char* smem, GAcc& g)
{
    constexpr int NA  = HAS_LO ? 2 : 1;
    constexpr int BO  = NA * G_ASZ;              // B offset (halfs)
    constexpr int STG = BO + 32*G_BLD;           // halfs per stage

    const int tid = threadIdx.x, lane = tid & 31, warp = tid >> 5;
    const int wm = warp >> 1, wn = warp & 1;
    __half* S = (__half*)smem;

    #pragma unroll
    for (int i = 0; i < 4; i++)
        #pragma unroll
        for (int j = 0; j < 8; j++)
            #pragma unroll
            for (int q = 0; q < 4; q++) g.c[i][j][q] = 0.f;

    auto load_stage = [&](int st, int k0) {
        __half* base = S + st * STG;
        #pragma unroll
        for (int i = 0; i < 4; i++) {
            int c = tid + i*128;
            int r = c >> 2, cc = (c & 3) * 8;
            cpa(sptr(base + r*G_ALD + cc), Ah + (size_t)(m0 + r)*DD + k0 + cc);
            if (HAS_LO)
                cpa(sptr(base + G_ASZ + r*G_ALD + cc), Al + (size_t)(m0 + r)*DD + k0 + cc);
        }
        #pragma unroll
        for (int i = 0; i < 4; i++) {
            int c = tid + i*128;
            int r = c >> 4, cc = (c & 15) * 8;
            cpa(sptr(base + BO + r*G_BLD + cc), W + (size_t)(k0 + r)*DD + n0 + cc);
        }
    };

    #pragma unroll
    for (int p = 0; p < NST-1; p++) { load_stage(p, p*32); CP_COMMIT; }

    const int arow = (lane & 7) + ((lane >> 3) & 1) * 8;
    const int acol = (lane >> 4) * 8;
    const int brow = lane & 15;
    const int bcol = (lane >> 4) * 8;

    for (int kt = 0; kt < 32; kt++) {
        if (NST == 3 && kt < 31) { CP_WAIT1; } else { CP_WAIT0; }
        __syncthreads();
        if (kt + NST - 1 < 32) { load_stage((kt + NST - 1) % NST, (kt + NST - 1)*32); CP_COMMIT; }

        __half* base = S + (kt % NST) * STG;
        #pragma unroll
        for (int k16 = 0; k16 < 2; k16++) {
            uint32_t ah[4][4], al[4][4];
            #pragma unroll
            for (int mt = 0; mt < 4; mt++) {
                uint32_t ad = sptr(base + (wm*64 + mt*16 + arow)*G_ALD + k16*16 + acol);
                ldsm4(ad, ah[mt]);
                if (HAS_LO) ldsm4(ad + (uint32_t)(G_ASZ*2), al[mt]);
            }
            #pragma unroll
            for (int nb = 0; nb < 4; nb++) {
                uint32_t b[4];
                ldsm4t(sptr(base + BO + (k16*16 + brow)*G_BLD + wn*64 + nb*16 + bcol), b);
                #pragma unroll
                for (int mt = 0; mt < 4; mt++) {
                    mma16816(g.c[mt][2*nb  ], ah[mt][0], ah[mt][1], ah[mt][2], ah[mt][3], b[0], b[1]);
                    mma16816(g.c[mt][2*nb+1], ah[mt][0], ah[mt][1], ah[mt][2], ah[mt][3], b[2], b[3]);
                    if (HAS_LO) {
                        mma16816(g.c[mt][2*nb  ], al[mt][0], al[mt][1], al[mt][2], al[mt][3], b[0], b[1]);
                        mma16816(g.c[mt][2*nb+1], al[mt][0], al[mt][1], al[mt][2], al[mt][3], b[2], b[3]);
                    }
                }
            }
        }
    }
}

#define GEMM_SMEM_QK  (2*(2*G_ASZ + 32*G_BLD)*2)   // 2 stages, hi+lo A  (58.4KB)
#define GEMM_SMEM_LO  (3*(1*G_ASZ + 32*G_BLD)*2)   // 3 stages, hi-only A (56.8KB)

// Q/K projection: z selects q/k. Q: hi only, scaled by log2(e). K: hi+lo.
__global__ __launch_bounds__(128) void projqk_kernel()
{
    extern __shared__ __align__(16) char smem[];
    int z = blockIdx.z;
    const __half* W = (z == 0) ? g_wq : g_wk;
    __half* Chi = (z == 0) ? g_qh : g_kh;
    float oscale = (z == 0) ? L2E : 1.0f;
    bool wlo = (z != 0);
    int m0 = blockIdx.x * 128, n0 = blockIdx.y * 128;

    GAcc g;
    gemm_mainloop<true, 2>(g_nh, g_nl, W, m0, n0, smem, g);

    int lane = threadIdx.x & 31, warp = threadIdx.x >> 5;
    int wm = warp >> 1, wn = warp & 1;
    #pragma unroll
    for (int mt = 0; mt < 4; mt++)
        #pragma unroll
        for (int nt = 0; nt < 8; nt++) {
            int row = m0 + wm*64 + mt*16 + (lane >> 2);
            int col = n0 + wn*64 + nt*8 + (lane & 3)*2;
            #pragma unroll
            for (int hfr = 0; hfr < 2; hfr++) {
                float v0 = g.c[mt][nt][hfr*2] * oscale, v1 = g.c[mt][nt][hfr*2+1] * oscale;
                __half h0 = __float2half_rn(v0), h1 = __float2half_rn(v1);
                size_t gi = (size_t)(row + hfr*8)*DD + col;
                *(__half2*)(Chi + gi) = __halves2half2(h0, h1);
                if (wlo) {
                    __half l0 = __float2half_rn(v0 - __half2float(h0));
                    __half l1 = __float2half_rn(v1 - __half2float(h1));
                    *(__half2*)(g_kl + gi) = __halves2half2(l0, l1);
                }
            }
        }
}

// V projection: A hi only, output hi only.
__global__ __launch_bounds__(128) void projv_kernel()
{
    extern __shared__ __align__(16) char smem[];
    int m0 = blockIdx.x * 128, n0 = blockIdx.y * 128;

    GAcc g;
    gemm_mainloop<false, 3>(g_nh, (const __half*)0, g_wv, m0, n0, smem, g);

    int lane = threadIdx.x & 31, warp = threadIdx.x >> 5;
    int wm = warp >> 1, wn = warp & 1;
    #pragma unroll
    for (int mt = 0; mt < 4; mt++)
        #pragma unroll
        for (int nt = 0; nt < 8; nt++) {
            int row = m0 + wm*64 + mt*16 + (lane >> 2);
            int col = n0 + wn*64 + nt*8 + (lane & 3)*2;
            #pragma unroll
            for (int hfr = 0; hfr < 2; hfr++) {
                size_t gi = (size_t)(row + hfr*8)*DD + col;
                *(__half2*)(g_vh + gi) =
                    __floats2half2_rn(g.c[mt][nt][hfr*2], g.c[mt][nt][hfr*2+1]);
            }
        }
}

// Output projection + residual -> fp32 out (A = ctx hi only)
__global__ __launch_bounds__(128) void oproj_kernel(
    const float* __restrict__ hid, float* __restrict__ out)
{
    extern __shared__ __align__(16) char smem[];
    int m0 = blockIdx.x * 128, n0 = blockIdx.y * 128;

    GAcc g;
    gemm_mainloop<false, 3>(g_ch, (const __half*)0, g_wo, m0, n0, smem, g);

    int lane = threadIdx.x & 31, warp = threadIdx.x >> 5;
    int wm = warp >> 1, wn = warp & 1;
    #pragma unroll
    for (int mt = 0; mt < 4; mt++)
        #pragma unroll
        for (int nt = 0; nt < 8; nt++) {
            int row = m0 + wm*64 + mt*16 + (lane >> 2);
            int col = n0 + wn*64 + nt*8 + (lane & 3)*2;
            #pragma unroll
            for (int hfr = 0; hfr < 2; hfr++) {
                size_t gi = (size_t)(row + hfr*8)*DD + col;
                float2 r = *(const float2*)(hid + gi);
                float2 o;
                o.x = g.c[mt][nt][hfr*2]   + r.x;
                o.y = g.c[mt][nt][hfr*2+1] + r.y;
                *(float2*)(out + gi) = o;
            }
        }
}

// ---------------- flash attention (FA2, register-resident, mma.sync) ----------------
// grid (SS/128=8, B*H=128), 256 threads = 8 warps, each warp 16 q-rows.
// BM=128, BN=64. S = qh·(kh+kl) (2-pass), V hi only.
// Logits pre-scaled by log2(e) -> ex2.
#define AT_LD 72
#define AT_KVA (64*AT_LD)      // halfs per KV array
#define AT_KVS (3*AT_KVA)      // halfs per stage (Kh,Kl,Vh)
#define ATTN_SMEM ((128*AT_LD + 2*AT_KVS)*2)

__global__ __launch_bounds__(256, 2) void attn_kernel()
{
    extern __shared__ __align__(16) char smem[];
    __half* Qh = (__half*)smem;                 // [128][AT_LD]
    __half* KV = Qh + 128*AT_LD;                // [2 stages][3 arrays][64*AT_LD]

    int tid = threadIdx.x, lane = tid & 31, warp = tid >> 5;
    int q0 = blockIdx.x * 128;
    int bh = blockIdx.y;
    int b = bh >> 4, h = bh & 15;
    size_t qg = ((size_t)(b*SS + q0)) * DD + h*DKK;

    #pragma unroll
    for (int i = 0; i < 4; i++) {
        int c = tid + i*256; int r = c >> 3, cc = (c & 7) * 8;
        cpa(sptr(Qh + r*AT_LD + cc), g_qh + qg + (size_t)r*DD + cc);
    }

    auto load_kv = [&](int st, int k0) {
        size_t kg = ((size_t)(b*SS + k0)) * DD + h*DKK;
        __half* s0 = KV + st * AT_KVS;
        #pragma unroll
        for (int i = 0; i < 2; i++) {
            int c = tid + i*256; int r = c >> 3, cc = (c & 7) * 8;
            cpa(sptr(s0 + 0*AT_KVA + r*AT_LD + cc), g_kh + kg + (size_t)r*DD + cc);
            cpa(sptr(s0 + 1*AT_KVA + r*AT_LD + cc), g_kl + kg + (size_t)r*DD + cc);
            cpa(sptr(s0 + 2*AT_KVA + r*AT_LD + cc), g_vh + kg + (size_t)r*DD + cc);
        }
    };
    load_kv(0, 0); CP_COMMIT;

    float o[8][4];
    #pragma unroll
    for (int i = 0; i < 8; i++)
        #pragma unroll
        for (int j = 0; j < 4; j++) o[i][j] = 0.f;
    float m0r = -1e30f, m1r = -1e30f, l0r = 0.f, l1r = 0.f;

    const int arow = (lane & 7) + ((lane >> 3) & 1) * 8;
    const int acol = (lane >> 4) * 8;
    const int trow = lane & 15;
    const int tcol = (lane >> 4) * 8;
    int qrow0 = warp*16 + (lane >> 2);
    const float* bias0 = g_bias + h*2048 + 1023 - (q0 + qrow0);

    for (int j = 0; j < 16; j++) {
        if (j + 1 < 16) { load_kv((j+1)&1, (j+1)*64); CP_COMMIT; CP_WAIT1; }
        else { CP_WAIT0; }
        __syncthreads();
        __half* st  = KV + (j & 1) * AT_KVS;
        __half* KhS = st;
        __half* VhS = st + 2*AT_KVA;

        float s[8][4];
        #pragma unroll
        for (int i = 0; i < 8; i++)
            #pragma unroll
            for (int q = 0; q < 4; q++) s[i][q] = 0.f;

        #pragma unroll
        for (int kk = 0; kk < 4; kk++) {
            uint32_t ah[4];
            uint32_t qa = sptr(Qh + (warp*16 + arow)*AT_LD + kk*16 + acol);
            ldsm4(qa, ah);
            #pragma unroll
            for (int nb = 0; nb < 4; nb++) {
                uint32_t bh4[4], bl4[4];
                uint32_t ka = sptr(KhS + (nb*16 + arow)*AT_LD + kk*16 + acol);
                ldsm4(ka, bh4);
                ldsm4(ka + (uint32_t)(AT_KVA*2), bl4);
                mma16816(s[2*nb  ], ah[0],ah[1],ah[2],ah[3], bh4[0], bh4[2]);
                mma16816(s[2*nb+1], ah[0],ah[1],ah[2],ah[3], bh4[1], bh4[3]);
                mma16816(s[2*nb  ], ah[0],ah[1],ah[2],ah[3], bl4[0], bl4[2]);
                mma16816(s[2*nb+1], ah[0],ah[1],ah[2],ah[3], bl4[1], bl4[3]);
            }
        }

        int kb = j*64;
        float mx0 = -1e30f, mx1 = -1e30f;
        #pragma unroll
        for (int nt = 0; nt < 8; nt++) {
            int col = kb + nt*8 + (lane & 3)*2;
            s[nt][0] += bias0[col];     s[nt][1] += bias0[col+1];
            s[nt][2] += bias0[col-8];   s[nt][3] += bias0[col-7];
            mx0 = fmaxf(mx0, fmaxf(s[nt][0], s[nt][1]));
            mx1 = fmaxf(mx1, fmaxf(s[nt][2], s[nt][3]));
        }
        mx0 = fmaxf(mx0, __shfl_xor_sync(0xffffffffu, mx0, 1));
        mx0 = fmaxf(mx0, __shfl_xor_sync(0xffffffffu, mx0, 2));
        mx1 = fmaxf(mx1, __shfl_xor_sync(0xffffffffu, mx1, 1));
        mx1 = fmaxf(mx1, __shfl_xor_sync(0xffffffffu, mx1, 2));
        float nm0 = fmaxf(m0r, mx0), nm1 = fmaxf(m1r, mx1);
        float sc0 = ex2f(m0r - nm0), sc1 = ex2f(m1r - nm1);
        m0r = nm0; m1r = nm1;

        float sum0 = 0.f, sum1 = 0.f;
        uint32_t u[8], w[8];
        #pragma unroll
        for (int nt = 0; nt < 8; nt++) {
            float p0 = ex2f(s[nt][0] - nm0), p1 = ex2f(s[nt][1] - nm0);
            float p2 = ex2f(s[nt][2] - nm1), p3 = ex2f(s[nt][3] - nm1);
            sum0 += p0 + p1; sum1 += p2 + p3;
            __half2 h01 = __floats2half2_rn(p0, p1);
            __half2 h23 = __floats2half2_rn(p2, p3);
            u[nt] = *(uint32_t*)&h01;
            w[nt] = *(uint32_t*)&h23;
            o[nt][0] *= sc0; o[nt][1] *= sc0;
            o[nt][2] *= sc1; o[nt][3] *= sc1;
        }
        sum0 += __shfl_xor_sync(0xffffffffu, sum0, 1);
        sum0 += __shfl_xor_sync(0xffffffffu, sum0, 2);
        sum1 += __shfl_xor_sync(0xffffffffu, sum1, 1);
        sum1 += __shfl_xor_sync(0xffffffffu, sum1, 2);
        l0r = l0r*sc0 + sum0;
        l1r = l1r*sc1 + sum1;

        #pragma unroll
        for (int kk = 0; kk < 4; kk++) {
            #pragma unroll
            for (int nb = 0; nb < 4; nb++) {
                uint32_t vh4[4];
                ldsm4t(sptr(VhS + (kk*16 + trow)*AT_LD + nb*16 + tcol), vh4);
                mma16816(o[2*nb  ], u[2*kk], w[2*kk], u[2*kk+1], w[2*kk+1], vh4[0], vh4[1]);
                mma16816(o[2*nb+1], u[2*kk], w[2*kk], u[2*kk+1], w[2*kk+1], vh4[2], vh4[3]);
            }
        }
        __syncthreads();
    }

    float inv0 = 1.f / l0r, inv1 = 1.f / l1r;
    #pragma unroll
    for (int nt = 0; nt < 8; nt++) {
        int col = h*DKK + nt*8 + (lane & 3)*2;
        size_t r0 = ((size_t)(b*SS + q0 + qrow0)) * DD + col;
        size_t r1 = r0 + (size_t)8*DD;
        float v0 = o[nt][0]*inv0, v1 = o[nt][1]*inv0;
        float v2 = o[nt][2]*inv1, v3 = o[nt][3]*inv1;
        *(__half2*)(g_ch + r0) = __floats2half2_rn(v0, v1);
        *(__half2*)(g_ch + r1) = __floats2half2_rn(v2, v3);
    }
}

// ---------------- launch ----------------
extern "C" void kernel_launch(void* const* d_in, const int* in_sizes, int n_in,
                              void* d_out, int out_size)
{
    const float* hid  = (const float*)d_in[0];
    const float* lnw  = (const float*)d_in[1];
    const float* wq   = (const float*)d_in[2];
    const float* wk   = (const float*)d_in[3];
    const float* wv   = (const float*)d_in[4];
    const float* wo   = (const float*)d_in[5];
    const float* relb = (const float*)d_in[6];
    float* out = (float*)d_out;

    cudaFuncSetAttribute(attn_kernel,   cudaFuncAttributeMaxDynamicSharedMemorySize, ATTN_SMEM);
    cudaFuncSetAttribute(projqk_kernel, cudaFuncAttributeMaxDynamicSharedMemorySize, GEMM_SMEM_QK);
    cudaFuncSetAttribute(projv_kernel,  cudaFuncAttributeMaxDynamicSharedMemorySize, GEMM_SMEM_LO);
    cudaFuncSetAttribute(oproj_kernel,  cudaFuncAttributeMaxDynamicSharedMemorySize, GEMM_SMEM_LO);

    prep_kernel<<<(DD*DD + 255)/256, 256>>>(wq, wk, wv, wo, relb);
    rms_kernel<<<MM, 256>>>(hid, lnw);
    projqk_kernel<<<dim3(MM/128, DD/128, 2), 128, GEMM_SMEM_QK>>>();
    projv_kernel<<<dim3(MM/128, DD/128), 128, GEMM_SMEM_LO>>>();
    attn_kernel<<<dim3(SS/128, BB*HH), 256, ATTN_SMEM>>>();
    oproj_kernel<<<dim3(MM/128, DD/128), 128, GEMM_SMEM_LO>>>(hid, out);
}